// round 2
// baseline (speedup 1.0000x reference)
#include <cuda_runtime.h>
#include <cstdint>
#include <cstddef>

#define N_NODES 100000
#define E_EDGES 1000000
#define D_DIM   64
#define NORM_INV 0.01f
#define LN_EPS  1e-5f

// Scratch: projected node features x = h @ W_lin^T + b  (25.6 MB)
__device__ float g_x[(size_t)N_NODES * D_DIM];

__device__ __forceinline__ float fsig(float v) {
    return __fdividef(1.0f, 1.0f + __expf(-v));
}

// ---------------------------------------------------------------------------
// Kernel 1: x = h @ W_lin^T + b_lin.  Writes x to g_x and also initializes
// d_out = x (residual), so the edge kernel can atomically accumulate into it.
// Warp handles 4 nodes; lane owns outputs d=lane and d=lane+32.
// ---------------------------------------------------------------------------
__global__ void linear_kernel(const float* __restrict__ h,
                              const float* __restrict__ W,   // [64][64] row-major
                              const float* __restrict__ b,
                              float* __restrict__ out_res)   // d_out, init = x
{
    __shared__ float  sW[64 * 68];
    __shared__ float  sb[64];
    __shared__ float4 sH[8][4][16];   // 8 warps x 4 nodes x 16 float4

    const int tid = threadIdx.x;
    for (int i = tid; i < 64 * 64; i += 256)
        sW[(i >> 6) * 68 + (i & 63)] = W[i];
    if (tid < 64) sb[tid] = b[tid];
    __syncthreads();

    const int lane = tid & 31;
    const int w    = tid >> 5;
    const int warpGlobal = blockIdx.x * 8 + w;
    const int nWarps     = gridDim.x * 8;

    const float4* sWf4 = (const float4*)sW;
    const float4* w0p  = sWf4 + lane * 17;          // 68 floats = 17 float4
    const float4* w1p  = sWf4 + (lane + 32) * 17;
    const float bj0 = sb[lane], bj1 = sb[lane + 32];
    const float4* hf4 = (const float4*)h;

    for (int nb = warpGlobal * 4; nb < N_NODES; nb += nWarps * 4) {
        // Coalesced load of 4 node rows into staging (2 nodes per half-warp)
        #pragma unroll
        for (int ep = 0; ep < 4; ep += 2) {
            const int e    = ep + (lane >> 4);
            const int li   = lane & 15;
            sH[w][e][li] = hf4[(size_t)(nb + e) * 16 + li];
        }
        __syncwarp();

        float acc0[4], acc1[4];
        #pragma unroll
        for (int e = 0; e < 4; e++) { acc0[e] = bj0; acc1[e] = bj1; }

        #pragma unroll
        for (int kk = 0; kk < 16; kk++) {
            const float4 wa = w0p[kk];
            const float4 wb = w1p[kk];
            #pragma unroll
            for (int e = 0; e < 4; e++) {
                const float4 xv = sH[w][e][kk];   // warp-uniform broadcast
                acc0[e] = fmaf(wa.x, xv.x, acc0[e]);
                acc0[e] = fmaf(wa.y, xv.y, acc0[e]);
                acc0[e] = fmaf(wa.z, xv.z, acc0[e]);
                acc0[e] = fmaf(wa.w, xv.w, acc0[e]);
                acc1[e] = fmaf(wb.x, xv.x, acc1[e]);
                acc1[e] = fmaf(wb.y, xv.y, acc1[e]);
                acc1[e] = fmaf(wb.z, xv.z, acc1[e]);
                acc1[e] = fmaf(wb.w, xv.w, acc1[e]);
            }
        }

        #pragma unroll
        for (int e = 0; e < 4; e++) {
            const size_t base = (size_t)(nb + e) * 64;
            g_x[base + lane]        = acc0[e];
            g_x[base + lane + 32]   = acc1[e];
            out_res[base + lane]      = acc0[e];
            out_res[base + lane + 32] = acc1[e];
        }
        __syncwarp();
    }
}

// ---------------------------------------------------------------------------
// Kernel 2: edge MLP + attention + scatter.
// Warp processes 4 edges per iteration. Lane owns hdn outputs j=lane, lane+32.
// W1 in smem padded to 132 floats/row; x_row|x_col staged per warp in smem.
// att folds edge_mask and 1/NORM_FACTOR; scatter = scalar REDG into d_out.
// ---------------------------------------------------------------------------
#define EDGE_SMEM ((64*132 + 64 + 64) * 4 + 8 * 4 * 32 * 16)   // 50688 bytes

__global__ void edge_kernel(const float* __restrict__ dist,
                            const int* __restrict__ edges,  // int32 [2][E]
                            const float* __restrict__ emask,
                            const float* __restrict__ W1,   // [64][129] row-major
                            const float* __restrict__ b1,
                            const float* __restrict__ W2,   // [64]
                            const float* __restrict__ b2p,  // [1]
                            float* __restrict__ agg)        // d_out (x + agg)
{
    extern __shared__ float smem[];
    float*  sW1 = smem;                    // 64*132 floats
    float*  sW2 = sW1 + 64 * 132;          // 64
    float*  sb1 = sW2 + 64;                // 64
    float4* sX  = (float4*)(sb1 + 64);     // [8 warps][4 edges][32 float4]

    const int tid = threadIdx.x;
    for (int i = tid; i < 64 * 129; i += 256)
        sW1[(i / 129) * 132 + (i % 129)] = W1[i];
    if (tid < 64) { sW2[tid] = W2[tid]; sb1[tid] = b1[tid]; }
    __syncthreads();

    const int lane = tid & 31;
    const int w    = tid >> 5;
    float4* sXw = sX + w * (4 * 32);

    const float b2  = b2p[0];
    const float w2a = sW2[lane],            w2b = sW2[lane + 32];
    const float bj0 = sb1[lane],            bj1 = sb1[lane + 32];
    const float wd0 = sW1[lane * 132 + 128], wd1 = sW1[(lane + 32) * 132 + 128];
    const float4* w0p = ((const float4*)sW1) + lane * 33;        // 132 floats = 33 f4
    const float4* w1p = ((const float4*)sW1) + (lane + 32) * 33;
    const float4* xf4 = (const float4*)g_x;

    const int warpGlobal = blockIdx.x * 8 + w;
    const int nWarps     = gridDim.x * 8;

    for (int eb = warpGlobal * 4; eb < E_EDGES; eb += nWarps * 4) {
        int   r[4];
        float dd[4], em[4];
        #pragma unroll
        for (int e = 0; e < 4; e++) {
            r[e]  = edges[eb + e];
            dd[e] = dist[eb + e];
            em[e] = emask[eb + e];
        }

        // Gather x[row] (lanes 0-15) and x[col] (lanes 16-31) into staging
        #pragma unroll
        for (int e = 0; e < 4; e++) {
            const int node = (lane < 16) ? r[e] : edges[E_EDGES + eb + e];
            sXw[e * 32 + lane] = xf4[(size_t)node * 16 + (lane & 15)];
        }
        __syncwarp();

        float acc0[4], acc1[4];
        #pragma unroll
        for (int e = 0; e < 4; e++) { acc0[e] = bj0; acc1[e] = bj1; }

        #pragma unroll
        for (int kk = 0; kk < 32; kk++) {
            const float4 wa = w0p[kk];
            const float4 wb = w1p[kk];
            #pragma unroll
            for (int e = 0; e < 4; e++) {
                const float4 xv = sXw[e * 32 + kk];   // broadcast
                acc0[e] = fmaf(wa.x, xv.x, acc0[e]);
                acc0[e] = fmaf(wa.y, xv.y, acc0[e]);
                acc0[e] = fmaf(wa.z, xv.z, acc0[e]);
                acc0[e] = fmaf(wa.w, xv.w, acc0[e]);
                acc1[e] = fmaf(wb.x, xv.x, acc1[e]);
                acc1[e] = fmaf(wb.y, xv.y, acc1[e]);
                acc1[e] = fmaf(wb.z, xv.z, acc1[e]);
                acc1[e] = fmaf(wb.w, xv.w, acc1[e]);
            }
        }

        float att[4];
        #pragma unroll
        for (int e = 0; e < 4; e++) {
            const float a0 = fmaf(dd[e], wd0, acc0[e]);
            const float a1 = fmaf(dd[e], wd1, acc1[e]);
            const float h0 = a0 * fsig(a0);               // silu
            const float h1 = a1 * fsig(a1);
            float p = fmaf(h0, w2a, h1 * w2b);
            #pragma unroll
            for (int off = 16; off; off >>= 1)
                p += __shfl_xor_sync(0xffffffffu, p, off);
            att[e] = fsig(p + b2) * em[e] * NORM_INV;
        }

        // Scatter att * x_col into agg[row].  Half-warps cover edge pairs.
        #pragma unroll
        for (int ep = 0; ep < 4; ep += 2) {
            const int   li = lane & 15;
            const int   e  = ep + (lane >> 4);            // smem index only
            const int   rr = (lane < 16) ? r[ep]   : r[ep + 1];
            const float a  = (lane < 16) ? att[ep] : att[ep + 1];
            const float4 v = sXw[e * 32 + 16 + li];       // x_col chunk
            float* dst = agg + (size_t)rr * 64 + li * 4;
            atomicAdd(dst + 0, v.x * a);
            atomicAdd(dst + 1, v.y * a);
            atomicAdd(dst + 2, v.z * a);
            atomicAdd(dst + 3, v.w * a);
        }
        __syncwarp();
    }
}

// ---------------------------------------------------------------------------
// Kernel 3: in-place LayerNorm + SiLU on d_out (which holds x + agg/100).
// Warp per row; lane owns d = 2*lane, 2*lane+1.
// ---------------------------------------------------------------------------
__global__ void ln_kernel(const float* __restrict__ g,
                          const float* __restrict__ bln,
                          float* __restrict__ io)
{
    const int lane = threadIdx.x & 31;
    const int w    = threadIdx.x >> 5;
    const int row  = blockIdx.x * 8 + w;
    if (row >= N_NODES) return;

    float2 v = ((const float2*)io)[(size_t)row * 32 + lane];

    float s = v.x + v.y;
    #pragma unroll
    for (int off = 16; off; off >>= 1)
        s += __shfl_xor_sync(0xffffffffu, s, off);
    const float mu = s * (1.0f / 64.0f);

    const float dx = v.x - mu, dy = v.y - mu;
    float q = dx * dx + dy * dy;
    #pragma unroll
    for (int off = 16; off; off >>= 1)
        q += __shfl_xor_sync(0xffffffffu, q, off);
    const float rs = rsqrtf(q * (1.0f / 64.0f) + LN_EPS);

    const float y0 = fmaf(dx * rs, __ldg(g + 2 * lane),     __ldg(bln + 2 * lane));
    const float y1 = fmaf(dy * rs, __ldg(g + 2 * lane + 1), __ldg(bln + 2 * lane + 1));

    float2 o;
    o.x = y0 * fsig(y0);
    o.y = y1 * fsig(y1);
    ((float2*)io)[(size_t)row * 32 + lane] = o;
}

// ---------------------------------------------------------------------------
// Launch: linear -> edge -> layernorm (default stream, graph-capturable).
// ---------------------------------------------------------------------------
extern "C" void kernel_launch(void* const* d_in, const int* in_sizes, int n_in,
                              void* d_out, int out_size)
{
    const float* h     = (const float*)d_in[0];
    const float* dist  = (const float*)d_in[1];
    const int*   edges = (const int*)d_in[2];   // JAX x64-disabled => int32
    /* d_in[3] node_mask: unused by the reference */
    const float* emask = (const float*)d_in[4];
    const float* Wlin  = (const float*)d_in[5];
    const float* blin  = (const float*)d_in[6];
    const float* W1    = (const float*)d_in[7];
    const float* b1    = (const float*)d_in[8];
    const float* W2    = (const float*)d_in[9];
    const float* b2    = (const float*)d_in[10];
    const float* lng   = (const float*)d_in[11];
    const float* lnb   = (const float*)d_in[12];
    float* out = (float*)d_out;

    cudaFuncSetAttribute(edge_kernel,
                         cudaFuncAttributeMaxDynamicSharedMemorySize, EDGE_SMEM);

    linear_kernel<<<592, 256>>>(h, Wlin, blin, out);
    edge_kernel<<<592, 256, EDGE_SMEM>>>(dist, edges, emask, W1, b1, W2, b2, out);
    ln_kernel<<<(N_NODES + 7) / 8, 256>>>(lng, lnb, out);
}

// round 3
// speedup vs baseline: 1.9466x; 1.9466x over previous
#include <cuda_runtime.h>
#include <cstdint>
#include <cstddef>

#define N_NODES 100000
#define E_EDGES 1000000
#define D_DIM   64
#define NORM_INV 0.01f
#define LN_EPS  1e-5f

// Scratch: x = h@Wlin^T+b, u = A@x, v = B@x  (A=W1[:,:64], B=W1[:,64:128])
__device__ float g_x[(size_t)N_NODES * D_DIM];
__device__ float g_u[(size_t)N_NODES * D_DIM];
__device__ float g_v[(size_t)N_NODES * D_DIM];

__device__ __forceinline__ float fsig(float v) {
    return __fdividef(1.0f, 1.0f + __expf(-v));
}

// ---------------------------------------------------------------------------
// Kernel 1 (prep): per node  x = Wlin@h + blin ;  u = A@x ;  v = B@x.
// Writes x to g_x and d_out (residual), u/v to g_u/g_v.
// Warp handles 8 nodes per iteration (halves per-node weight LDS traffic).
// Weights in smem padded to 68 floats/row.
// ---------------------------------------------------------------------------
#define PREP_SMEM ((3 * 64 * 68 + 64) * 4 + 8 * 8 * 16 * 16)   // 68,864 B

__global__ void prep_kernel(const float* __restrict__ h,
                            const float* __restrict__ Wlin,  // [64][64]
                            const float* __restrict__ blin,  // [64]
                            const float* __restrict__ W1,    // [64][129]
                            float* __restrict__ out_res)     // d_out := x
{
    extern __shared__ float smem[];
    float*  sWx = smem;                   // 64*68
    float*  sWa = sWx + 64 * 68;          // 64*68
    float*  sWb = sWa + 64 * 68;          // 64*68
    float*  sb  = sWb + 64 * 68;          // 64
    float4* sH  = (float4*)(sb + 64);     // [8 warps][8 nodes][16 f4]

    const int tid = threadIdx.x;
    for (int i = tid; i < 64 * 64; i += 256) {
        const int r = i >> 6, c = i & 63;
        sWx[r * 68 + c] = Wlin[i];
        sWa[r * 68 + c] = W1[r * 129 + c];
        sWb[r * 68 + c] = W1[r * 129 + 64 + c];
    }
    if (tid < 64) sb[tid] = blin[tid];
    __syncthreads();

    const int lane = tid & 31;
    const int w    = tid >> 5;
    const int warpGlobal = blockIdx.x * 8 + w;
    const int nWarps     = gridDim.x * 8;

    const float4* wx0 = ((const float4*)sWx) + lane * 17;
    const float4* wx1 = ((const float4*)sWx) + (lane + 32) * 17;
    const float4* wa0 = ((const float4*)sWa) + lane * 17;
    const float4* wa1 = ((const float4*)sWa) + (lane + 32) * 17;
    const float4* wb0 = ((const float4*)sWb) + lane * 17;
    const float4* wb1 = ((const float4*)sWb) + (lane + 32) * 17;
    const float bj0 = sb[lane], bj1 = sb[lane + 32];
    const float4* hf4 = (const float4*)h;
    float4* sHw = sH + w * (8 * 16);
    float*  sHwF = (float*)sHw;

    for (int nb = warpGlobal * 8; nb < N_NODES; nb += nWarps * 8) {
        // Stage 8 h rows (2 nodes per half-warp, 4 passes)
        #pragma unroll
        for (int ep = 0; ep < 8; ep += 2) {
            const int e  = ep + (lane >> 4);
            const int li = lane & 15;
            sHw[e * 16 + li] = hf4[(size_t)(nb + e) * 16 + li];
        }
        __syncwarp();

        // GEMM 1: x = Wlin @ h + b
        float acc0[8], acc1[8];
        #pragma unroll
        for (int e = 0; e < 8; e++) { acc0[e] = bj0; acc1[e] = bj1; }
        #pragma unroll
        for (int kk = 0; kk < 16; kk++) {
            const float4 a = wx0[kk], b = wx1[kk];
            #pragma unroll
            for (int e = 0; e < 8; e++) {
                const float4 xv = sHw[e * 16 + kk];
                acc0[e] = fmaf(a.x, xv.x, acc0[e]);
                acc0[e] = fmaf(a.y, xv.y, acc0[e]);
                acc0[e] = fmaf(a.z, xv.z, acc0[e]);
                acc0[e] = fmaf(a.w, xv.w, acc0[e]);
                acc1[e] = fmaf(b.x, xv.x, acc1[e]);
                acc1[e] = fmaf(b.y, xv.y, acc1[e]);
                acc1[e] = fmaf(b.z, xv.z, acc1[e]);
                acc1[e] = fmaf(b.w, xv.w, acc1[e]);
            }
        }
        __syncwarp();
        // Overwrite staging with x
        #pragma unroll
        for (int e = 0; e < 8; e++) {
            sHwF[e * 64 + lane]      = acc0[e];
            sHwF[e * 64 + lane + 32] = acc1[e];
        }
        __syncwarp();
        // Vectorized store of x to g_x and residual out
        #pragma unroll
        for (int ep = 0; ep < 8; ep += 2) {
            const int e  = ep + (lane >> 4);
            const int li = lane & 15;
            const float4 val = sHw[e * 16 + li];
            ((float4*)g_x)[(size_t)(nb + e) * 16 + li]   = val;
            ((float4*)out_res)[(size_t)(nb + e) * 16 + li] = val;
        }

        // GEMM 2: u = A @ x
        #pragma unroll
        for (int e = 0; e < 8; e++) { acc0[e] = 0.f; acc1[e] = 0.f; }
        #pragma unroll
        for (int kk = 0; kk < 16; kk++) {
            const float4 a = wa0[kk], b = wa1[kk];
            #pragma unroll
            for (int e = 0; e < 8; e++) {
                const float4 xv = sHw[e * 16 + kk];
                acc0[e] = fmaf(a.x, xv.x, acc0[e]);
                acc0[e] = fmaf(a.y, xv.y, acc0[e]);
                acc0[e] = fmaf(a.z, xv.z, acc0[e]);
                acc0[e] = fmaf(a.w, xv.w, acc0[e]);
                acc1[e] = fmaf(b.x, xv.x, acc1[e]);
                acc1[e] = fmaf(b.y, xv.y, acc1[e]);
                acc1[e] = fmaf(b.z, xv.z, acc1[e]);
                acc1[e] = fmaf(b.w, xv.w, acc1[e]);
            }
        }
        #pragma unroll
        for (int e = 0; e < 8; e++) {
            const size_t base = (size_t)(nb + e) * 64;
            g_u[base + lane]      = acc0[e];
            g_u[base + lane + 32] = acc1[e];
        }

        // GEMM 3: v = B @ x
        #pragma unroll
        for (int e = 0; e < 8; e++) { acc0[e] = 0.f; acc1[e] = 0.f; }
        #pragma unroll
        for (int kk = 0; kk < 16; kk++) {
            const float4 a = wb0[kk], b = wb1[kk];
            #pragma unroll
            for (int e = 0; e < 8; e++) {
                const float4 xv = sHw[e * 16 + kk];
                acc0[e] = fmaf(a.x, xv.x, acc0[e]);
                acc0[e] = fmaf(a.y, xv.y, acc0[e]);
                acc0[e] = fmaf(a.z, xv.z, acc0[e]);
                acc0[e] = fmaf(a.w, xv.w, acc0[e]);
                acc1[e] = fmaf(b.x, xv.x, acc1[e]);
                acc1[e] = fmaf(b.y, xv.y, acc1[e]);
                acc1[e] = fmaf(b.z, xv.z, acc1[e]);
                acc1[e] = fmaf(b.w, xv.w, acc1[e]);
            }
        }
        #pragma unroll
        for (int e = 0; e < 8; e++) {
            const size_t base = (size_t)(nb + e) * 64;
            g_v[base + lane]      = acc0[e];
            g_v[base + lane + 32] = acc1[e];
        }
        __syncwarp();
    }
}

// ---------------------------------------------------------------------------
// Kernel 2 (edge): hdn = silu(u[row]+v[col]+wd*d+b1); att = sig(W2.hdn+b2);
// scatter att*x_col into d_out[row]. Half-warp per edge (lane li owns dims
// 4*li..4*li+3), 4 edges per warp-iteration. No shared memory, no GEMM.
// ---------------------------------------------------------------------------
__global__ void edge_kernel(const float* __restrict__ dist,
                            const int* __restrict__ edges,  // int32 [2][E]
                            const float* __restrict__ emask,
                            const float* __restrict__ W1,   // [64][129]
                            const float* __restrict__ b1,
                            const float* __restrict__ W2,   // [64]
                            const float* __restrict__ b2p,
                            float* __restrict__ agg)        // d_out
{
    const int lane = threadIdx.x & 31;
    const int w    = threadIdx.x >> 5;
    const int hw   = lane >> 4;      // which edge of the pair
    const int li   = lane & 15;      // dim group within edge

    // Per-lane constants for dims 4*li .. 4*li+3
    const float4 w2_4 = ((const float4*)W2)[li];
    const float4 b1_4 = ((const float4*)b1)[li];
    float4 wd_4;
    wd_4.x = __ldg(W1 + (size_t)(li * 4 + 0) * 129 + 128);
    wd_4.y = __ldg(W1 + (size_t)(li * 4 + 1) * 129 + 128);
    wd_4.z = __ldg(W1 + (size_t)(li * 4 + 2) * 129 + 128);
    wd_4.w = __ldg(W1 + (size_t)(li * 4 + 3) * 129 + 128);
    const float b2 = b2p[0];

    const float4* uf4 = (const float4*)g_u;
    const float4* vf4 = (const float4*)g_v;
    const float4* xf4 = (const float4*)g_x;

    const int warpGlobal = blockIdx.x * 8 + w;
    const int nWarps     = gridDim.x * 8;

    for (int eb = warpGlobal * 4; eb < E_EDGES; eb += nWarps * 4) {
        #pragma unroll
        for (int s = 0; s < 2; s++) {
            const int e   = eb + s * 2 + hw;            // E%4==0 -> in range
            const int row = edges[e];
            const int col = edges[E_EDGES + e];
            const float d  = dist[e];
            const float em = emask[e];

            const float4 u4 = uf4[(size_t)row * 16 + li];
            const float4 v4 = vf4[(size_t)col * 16 + li];
            const float4 x4 = xf4[(size_t)col * 16 + li];

            float4 t;
            t.x = fmaf(d, wd_4.x, u4.x + v4.x + b1_4.x);
            t.y = fmaf(d, wd_4.y, u4.y + v4.y + b1_4.y);
            t.z = fmaf(d, wd_4.z, u4.z + v4.z + b1_4.z);
            t.w = fmaf(d, wd_4.w, u4.w + v4.w + b1_4.w);

            const float h0 = t.x * fsig(t.x);
            const float h1 = t.y * fsig(t.y);
            const float h2 = t.z * fsig(t.z);
            const float h3 = t.w * fsig(t.w);

            float p = fmaf(h0, w2_4.x,
                      fmaf(h1, w2_4.y,
                      fmaf(h2, w2_4.z, h3 * w2_4.w)));
            #pragma unroll
            for (int off = 8; off; off >>= 1)          // reduce within 16 lanes
                p += __shfl_xor_sync(0xffffffffu, p, off);

            const float att = fsig(p + b2) * em * NORM_INV;

            float* dst = agg + (size_t)row * 64 + li * 4;
            atomicAdd(dst + 0, x4.x * att);
            atomicAdd(dst + 1, x4.y * att);
            atomicAdd(dst + 2, x4.z * att);
            atomicAdd(dst + 3, x4.w * att);
        }
    }
}

// ---------------------------------------------------------------------------
// Kernel 3: in-place LayerNorm + SiLU on d_out.
// ---------------------------------------------------------------------------
__global__ void ln_kernel(const float* __restrict__ g,
                          const float* __restrict__ bln,
                          float* __restrict__ io)
{
    const int lane = threadIdx.x & 31;
    const int w    = threadIdx.x >> 5;
    const int row  = blockIdx.x * 8 + w;
    if (row >= N_NODES) return;

    float2 v = ((const float2*)io)[(size_t)row * 32 + lane];

    float s = v.x + v.y;
    #pragma unroll
    for (int off = 16; off; off >>= 1)
        s += __shfl_xor_sync(0xffffffffu, s, off);
    const float mu = s * (1.0f / 64.0f);

    const float dx = v.x - mu, dy = v.y - mu;
    float q = dx * dx + dy * dy;
    #pragma unroll
    for (int off = 16; off; off >>= 1)
        q += __shfl_xor_sync(0xffffffffu, q, off);
    const float rs = rsqrtf(q * (1.0f / 64.0f) + LN_EPS);

    const float y0 = fmaf(dx * rs, __ldg(g + 2 * lane),     __ldg(bln + 2 * lane));
    const float y1 = fmaf(dy * rs, __ldg(g + 2 * lane + 1), __ldg(bln + 2 * lane + 1));

    float2 o;
    o.x = y0 * fsig(y0);
    o.y = y1 * fsig(y1);
    ((float2*)io)[(size_t)row * 32 + lane] = o;
}

// ---------------------------------------------------------------------------
// Launch: prep -> edge -> layernorm.
// ---------------------------------------------------------------------------
extern "C" void kernel_launch(void* const* d_in, const int* in_sizes, int n_in,
                              void* d_out, int out_size)
{
    const float* h     = (const float*)d_in[0];
    const float* dist  = (const float*)d_in[1];
    const int*   edges = (const int*)d_in[2];   // JAX x64-disabled => int32
    /* d_in[3] node_mask: unused by the reference */
    const float* emask = (const float*)d_in[4];
    const float* Wlin  = (const float*)d_in[5];
    const float* blin  = (const float*)d_in[6];
    const float* W1    = (const float*)d_in[7];
    const float* b1    = (const float*)d_in[8];
    const float* W2    = (const float*)d_in[9];
    const float* b2    = (const float*)d_in[10];
    const float* lng   = (const float*)d_in[11];
    const float* lnb   = (const float*)d_in[12];
    float* out = (float*)d_out;

    cudaFuncSetAttribute(prep_kernel,
                         cudaFuncAttributeMaxDynamicSharedMemorySize, PREP_SMEM);

    prep_kernel<<<592, 256, PREP_SMEM>>>(h, Wlin, blin, W1, out);
    edge_kernel<<<1184, 256>>>(dist, edges, emask, W1, b1, W2, b2, out);
    ln_kernel<<<(N_NODES + 7) / 8, 256>>>(lng, lnb, out);
}

// round 4
// speedup vs baseline: 3.0041x; 1.5432x over previous
#include <cuda_runtime.h>
#include <cstdint>
#include <cstddef>

#define N_NODES 100000
#define E_EDGES 1000000
#define D_DIM   64
#define NORM_INV 0.01f
#define LN_EPS  1e-5f

// Scratch: x = h@Wlin^T+b, u = A@x, v = B@x  (A=W1[:,:64], B=W1[:,64:128])
__device__ float g_x[(size_t)N_NODES * D_DIM];
__device__ float g_u[(size_t)N_NODES * D_DIM];
__device__ float g_v[(size_t)N_NODES * D_DIM];

__device__ __forceinline__ float fsig(float v) {
    return __fdividef(1.0f, 1.0f + __expf(-v));
}

__device__ __forceinline__ void red_add_v4(float* dst, float a, float b,
                                           float c, float d) {
    asm volatile("red.global.add.v4.f32 [%0], {%1, %2, %3, %4};"
                 :: "l"(dst), "f"(a), "f"(b), "f"(c), "f"(d) : "memory");
}

// ---------------------------------------------------------------------------
// Kernel 1 (prep): per node  x = Wlin@h + blin ;  u = A@x ;  v = B@x.
// 4 nodes per warp-iteration (moderate reg pressure -> high occupancy).
// Weights in smem padded to 68 floats/row. x round-trips through staging.
// ---------------------------------------------------------------------------
#define PREP_SMEM ((3 * 64 * 68 + 64) * 4 + 8 * 4 * 16 * 16)   // 60,672 B

__global__ void __launch_bounds__(256, 3)
prep_kernel(const float* __restrict__ h,
            const float* __restrict__ Wlin,  // [64][64]
            const float* __restrict__ blin,  // [64]
            const float* __restrict__ W1,    // [64][129]
            float* __restrict__ out_res)     // d_out := x
{
    extern __shared__ float smem[];
    float*  sWx = smem;                   // 64*68
    float*  sWa = sWx + 64 * 68;
    float*  sWb = sWa + 64 * 68;
    float*  sb  = sWb + 64 * 68;          // 64
    float4* sH  = (float4*)(sb + 64);     // [8 warps][4 nodes][16 f4]

    const int tid = threadIdx.x;
    for (int i = tid; i < 64 * 64; i += 256) {
        const int r = i >> 6, c = i & 63;
        sWx[r * 68 + c] = Wlin[i];
        sWa[r * 68 + c] = W1[r * 129 + c];
        sWb[r * 68 + c] = W1[r * 129 + 64 + c];
    }
    if (tid < 64) sb[tid] = blin[tid];
    __syncthreads();

    const int lane = tid & 31;
    const int w    = tid >> 5;
    const int warpGlobal = blockIdx.x * 8 + w;
    const int nWarps     = gridDim.x * 8;

    const float4* wx0 = ((const float4*)sWx) + lane * 17;
    const float4* wx1 = ((const float4*)sWx) + (lane + 32) * 17;
    const float4* wa0 = ((const float4*)sWa) + lane * 17;
    const float4* wa1 = ((const float4*)sWa) + (lane + 32) * 17;
    const float4* wb0 = ((const float4*)sWb) + lane * 17;
    const float4* wb1 = ((const float4*)sWb) + (lane + 32) * 17;
    const float bj0 = sb[lane], bj1 = sb[lane + 32];
    const float4* hf4 = (const float4*)h;
    float4* sHw  = sH + w * (4 * 16);
    float*  sHwF = (float*)sHw;

    for (int nb = warpGlobal * 4; nb < N_NODES; nb += nWarps * 4) {
        // Stage 4 h rows (2 nodes per half-warp, 2 passes)
        #pragma unroll
        for (int ep = 0; ep < 4; ep += 2) {
            const int e  = ep + (lane >> 4);
            const int li = lane & 15;
            sHw[e * 16 + li] = hf4[(size_t)(nb + e) * 16 + li];
        }
        __syncwarp();

        float acc0[4], acc1[4];

        // GEMM 1: x = Wlin @ h + b
        #pragma unroll
        for (int e = 0; e < 4; e++) { acc0[e] = bj0; acc1[e] = bj1; }
        #pragma unroll 4
        for (int kk = 0; kk < 16; kk++) {
            const float4 a = wx0[kk], b = wx1[kk];
            #pragma unroll
            for (int e = 0; e < 4; e++) {
                const float4 xv = sHw[e * 16 + kk];
                acc0[e] = fmaf(a.x, xv.x, acc0[e]);
                acc0[e] = fmaf(a.y, xv.y, acc0[e]);
                acc0[e] = fmaf(a.z, xv.z, acc0[e]);
                acc0[e] = fmaf(a.w, xv.w, acc0[e]);
                acc1[e] = fmaf(b.x, xv.x, acc1[e]);
                acc1[e] = fmaf(b.y, xv.y, acc1[e]);
                acc1[e] = fmaf(b.z, xv.z, acc1[e]);
                acc1[e] = fmaf(b.w, xv.w, acc1[e]);
            }
        }
        __syncwarp();
        // x -> staging (input of GEMM 2/3)
        #pragma unroll
        for (int e = 0; e < 4; e++) {
            sHwF[e * 64 + lane]      = acc0[e];
            sHwF[e * 64 + lane + 32] = acc1[e];
        }
        __syncwarp();
        // x -> g_x and residual out (vectorized)
        #pragma unroll
        for (int ep = 0; ep < 4; ep += 2) {
            const int e  = ep + (lane >> 4);
            const int li = lane & 15;
            const float4 val = sHw[e * 16 + li];
            ((float4*)g_x)[(size_t)(nb + e) * 16 + li]     = val;
            ((float4*)out_res)[(size_t)(nb + e) * 16 + li] = val;
        }

        // GEMM 2: u = A @ x
        #pragma unroll
        for (int e = 0; e < 4; e++) { acc0[e] = 0.f; acc1[e] = 0.f; }
        #pragma unroll 4
        for (int kk = 0; kk < 16; kk++) {
            const float4 a = wa0[kk], b = wa1[kk];
            #pragma unroll
            for (int e = 0; e < 4; e++) {
                const float4 xv = sHw[e * 16 + kk];
                acc0[e] = fmaf(a.x, xv.x, acc0[e]);
                acc0[e] = fmaf(a.y, xv.y, acc0[e]);
                acc0[e] = fmaf(a.z, xv.z, acc0[e]);
                acc0[e] = fmaf(a.w, xv.w, acc0[e]);
                acc1[e] = fmaf(b.x, xv.x, acc1[e]);
                acc1[e] = fmaf(b.y, xv.y, acc1[e]);
                acc1[e] = fmaf(b.z, xv.z, acc1[e]);
                acc1[e] = fmaf(b.w, xv.w, acc1[e]);
            }
        }
        #pragma unroll
        for (int e = 0; e < 4; e++) {
            const size_t base = (size_t)(nb + e) * 64;
            g_u[base + lane]      = acc0[e];
            g_u[base + lane + 32] = acc1[e];
        }

        // GEMM 3: v = B @ x
        #pragma unroll
        for (int e = 0; e < 4; e++) { acc0[e] = 0.f; acc1[e] = 0.f; }
        #pragma unroll 4
        for (int kk = 0; kk < 16; kk++) {
            const float4 a = wb0[kk], b = wb1[kk];
            #pragma unroll
            for (int e = 0; e < 4; e++) {
                const float4 xv = sHw[e * 16 + kk];
                acc0[e] = fmaf(a.x, xv.x, acc0[e]);
                acc0[e] = fmaf(a.y, xv.y, acc0[e]);
                acc0[e] = fmaf(a.z, xv.z, acc0[e]);
                acc0[e] = fmaf(a.w, xv.w, acc0[e]);
                acc1[e] = fmaf(b.x, xv.x, acc1[e]);
                acc1[e] = fmaf(b.y, xv.y, acc1[e]);
                acc1[e] = fmaf(b.z, xv.z, acc1[e]);
                acc1[e] = fmaf(b.w, xv.w, acc1[e]);
            }
        }
        #pragma unroll
        for (int e = 0; e < 4; e++) {
            const size_t base = (size_t)(nb + e) * 64;
            g_v[base + lane]      = acc0[e];
            g_v[base + lane + 32] = acc1[e];
        }
        __syncwarp();
    }
}

// ---------------------------------------------------------------------------
// Kernel 2 (edge): hdn = silu(u[row]+v[col]+wd*d+b1); att = sig(W2.hdn+b2);
// scatter att*x_col into d_out[row] with red.global.add.v4.f32.
// Half-warp per edge (lane li owns dims 4*li..4*li+3), 4 edges/warp-iter.
// ---------------------------------------------------------------------------
__global__ void edge_kernel(const float* __restrict__ dist,
                            const int* __restrict__ edges,  // int32 [2][E]
                            const float* __restrict__ emask,
                            const float* __restrict__ W1,   // [64][129]
                            const float* __restrict__ b1,
                            const float* __restrict__ W2,   // [64]
                            const float* __restrict__ b2p,
                            float* __restrict__ agg)        // d_out
{
    const int lane = threadIdx.x & 31;
    const int w    = threadIdx.x >> 5;
    const int hw   = lane >> 4;      // which edge of the pair
    const int li   = lane & 15;      // dim group within edge

    const float4 w2_4 = ((const float4*)W2)[li];
    const float4 b1_4 = ((const float4*)b1)[li];
    float4 wd_4;
    wd_4.x = __ldg(W1 + (size_t)(li * 4 + 0) * 129 + 128);
    wd_4.y = __ldg(W1 + (size_t)(li * 4 + 1) * 129 + 128);
    wd_4.z = __ldg(W1 + (size_t)(li * 4 + 2) * 129 + 128);
    wd_4.w = __ldg(W1 + (size_t)(li * 4 + 3) * 129 + 128);
    const float b2 = b2p[0];

    const float4* uf4 = (const float4*)g_u;
    const float4* vf4 = (const float4*)g_v;
    const float4* xf4 = (const float4*)g_x;

    const int warpGlobal = blockIdx.x * 8 + w;
    const int nWarps     = gridDim.x * 8;

    for (int eb = warpGlobal * 4; eb < E_EDGES; eb += nWarps * 4) {
        #pragma unroll
        for (int s = 0; s < 2; s++) {
            const int e   = eb + s * 2 + hw;            // E%4==0 -> in range
            const int row = __ldg(edges + e);
            const int col = __ldg(edges + E_EDGES + e);
            const float d  = __ldg(dist + e);
            const float em = __ldg(emask + e);

            const float4 u4 = __ldg(uf4 + (size_t)row * 16 + li);
            const float4 v4 = __ldg(vf4 + (size_t)col * 16 + li);
            const float4 x4 = __ldg(xf4 + (size_t)col * 16 + li);

            float4 t;
            t.x = fmaf(d, wd_4.x, u4.x + v4.x + b1_4.x);
            t.y = fmaf(d, wd_4.y, u4.y + v4.y + b1_4.y);
            t.z = fmaf(d, wd_4.z, u4.z + v4.z + b1_4.z);
            t.w = fmaf(d, wd_4.w, u4.w + v4.w + b1_4.w);

            const float h0 = t.x * fsig(t.x);
            const float h1 = t.y * fsig(t.y);
            const float h2 = t.z * fsig(t.z);
            const float h3 = t.w * fsig(t.w);

            float p = fmaf(h0, w2_4.x,
                      fmaf(h1, w2_4.y,
                      fmaf(h2, w2_4.z, h3 * w2_4.w)));
            #pragma unroll
            for (int off = 8; off; off >>= 1)          // reduce within 16 lanes
                p += __shfl_xor_sync(0xffffffffu, p, off);

            const float att = fsig(p + b2) * em * NORM_INV;

            float* dst = agg + (size_t)row * 64 + li * 4;
            red_add_v4(dst, x4.x * att, x4.y * att, x4.z * att, x4.w * att);
        }
    }
}

// ---------------------------------------------------------------------------
// Kernel 3: in-place LayerNorm + SiLU on d_out.
// ---------------------------------------------------------------------------
__global__ void ln_kernel(const float* __restrict__ g,
                          const float* __restrict__ bln,
                          float* __restrict__ io)
{
    const int lane = threadIdx.x & 31;
    const int w    = threadIdx.x >> 5;
    const int row  = blockIdx.x * 8 + w;
    if (row >= N_NODES) return;

    float2 v = ((const float2*)io)[(size_t)row * 32 + lane];

    float s = v.x + v.y;
    #pragma unroll
    for (int off = 16; off; off >>= 1)
        s += __shfl_xor_sync(0xffffffffu, s, off);
    const float mu = s * (1.0f / 64.0f);

    const float dx = v.x - mu, dy = v.y - mu;
    float q = dx * dx + dy * dy;
    #pragma unroll
    for (int off = 16; off; off >>= 1)
        q += __shfl_xor_sync(0xffffffffu, q, off);
    const float rs = rsqrtf(q * (1.0f / 64.0f) + LN_EPS);

    const float y0 = fmaf(dx * rs, __ldg(g + 2 * lane),     __ldg(bln + 2 * lane));
    const float y1 = fmaf(dy * rs, __ldg(g + 2 * lane + 1), __ldg(bln + 2 * lane + 1));

    float2 o;
    o.x = y0 * fsig(y0);
    o.y = y1 * fsig(y1);
    ((float2*)io)[(size_t)row * 32 + lane] = o;
}

// ---------------------------------------------------------------------------
// Launch: prep -> edge -> layernorm.
// ---------------------------------------------------------------------------
extern "C" void kernel_launch(void* const* d_in, const int* in_sizes, int n_in,
                              void* d_out, int out_size)
{
    const float* h     = (const float*)d_in[0];
    const float* dist  = (const float*)d_in[1];
    const int*   edges = (const int*)d_in[2];   // JAX x64-disabled => int32
    /* d_in[3] node_mask: unused by the reference */
    const float* emask = (const float*)d_in[4];
    const float* Wlin  = (const float*)d_in[5];
    const float* blin  = (const float*)d_in[6];
    const float* W1    = (const float*)d_in[7];
    const float* b1    = (const float*)d_in[8];
    const float* W2    = (const float*)d_in[9];
    const float* b2    = (const float*)d_in[10];
    const float* lng   = (const float*)d_in[11];
    const float* lnb   = (const float*)d_in[12];
    float* out = (float*)d_out;

    cudaFuncSetAttribute(prep_kernel,
                         cudaFuncAttributeMaxDynamicSharedMemorySize, PREP_SMEM);

    prep_kernel<<<592, 256, PREP_SMEM>>>(h, Wlin, blin, W1, out);
    edge_kernel<<<1184, 256>>>(dist, edges, emask, W1, b1, W2, b2, out);
    ln_kernel<<<(N_NODES + 7) / 8, 256>>>(lng, lnb, out);
}

// round 5
// speedup vs baseline: 3.6995x; 1.2315x over previous
#include <cuda_runtime.h>
#include <cuda_bf16.h>
#include <cstdint>
#include <cstddef>

#define N_NODES 100000
#define E_EDGES 1000000
#define D_DIM   64
#define NORM_INV 0.01f
#define LN_EPS  1e-5f

// Composite stacked weights: rows 0-63 Wlin, 64-127 Wu=A@Wlin, 128-191 Wv=B@Wlin
__device__ float g_Ws[192 * 64];
__device__ float g_bs[192];           // {blin, A@blin, B@blin}
// Per-node features for the edge kernel (bf16; att path is /100-damped)
__device__ __nv_bfloat16 g_uv[(size_t)N_NODES * 128];  // [node][0:64]=u, [64:128]=v
__device__ __nv_bfloat16 g_xc[(size_t)N_NODES * 64];   // x copy for scatter values

__device__ __forceinline__ float fsig(float v) {
    return __fdividef(1.0f, 1.0f + __expf(-v));
}

__device__ __forceinline__ void red_add_v4(float* dst, float a, float b,
                                           float c, float d) {
    asm volatile("red.global.add.v4.f32 [%0], {%1, %2, %3, %4};"
                 :: "l"(dst), "f"(a), "f"(b), "f"(c), "f"(d) : "memory");
}

__device__ __forceinline__ float4 bf16x4_to_f4(uint2 r) {
    const float2 a = __bfloat1622float2(*reinterpret_cast<__nv_bfloat162*>(&r.x));
    const float2 b = __bfloat1622float2(*reinterpret_cast<__nv_bfloat162*>(&r.y));
    return make_float4(a.x, a.y, b.x, b.y);
}

// ---------------------------------------------------------------------------
// Kernel 0 (compose): Wu = A@Wlin, Wv = B@Wlin, bu = A@blin, bv = B@blin,
// stacked into g_Ws / g_bs.  A = W1[:, :64], B = W1[:, 64:128].
// grid = 16 blocks x 256 threads (1 output element per thread for Wu & Wv).
// ---------------------------------------------------------------------------
__global__ void compose_kernel(const float* __restrict__ Wlin,
                               const float* __restrict__ blin,
                               const float* __restrict__ W1)
{
    __shared__ float sWlin[4096], sA[4096], sB[4096];
    const int tid = threadIdx.x;
    for (int i = tid; i < 4096; i += 256) {
        sWlin[i] = Wlin[i];
        const int r = i >> 6, c = i & 63;
        sA[i] = W1[r * 129 + c];
        sB[i] = W1[r * 129 + 64 + c];
    }
    __syncthreads();

    if (blockIdx.x == 0) {
        for (int i = tid; i < 4096; i += 256) g_Ws[i] = sWlin[i];
        if (tid < 64) {
            g_bs[tid] = blin[tid];
            float su = 0.f, sv = 0.f;
            for (int m = 0; m < 64; m++) {
                const float bm = __ldg(blin + m);
                su = fmaf(sA[tid * 64 + m], bm, su);
                sv = fmaf(sB[tid * 64 + m], bm, sv);
            }
            g_bs[64 + tid]  = su;
            g_bs[128 + tid] = sv;
        }
    }

    for (int idx = blockIdx.x * 256 + tid; idx < 4096; idx += gridDim.x * 256) {
        const int j = idx >> 6, k = idx & 63;
        float su = 0.f, sv = 0.f;
        #pragma unroll 8
        for (int m = 0; m < 64; m++) {
            const float w = sWlin[m * 64 + k];
            su = fmaf(sA[j * 64 + m], w, su);
            sv = fmaf(sB[j * 64 + m], w, sv);
        }
        g_Ws[4096 + idx] = su;
        g_Ws[8192 + idx] = sv;
    }
}

// ---------------------------------------------------------------------------
// Kernel 1 (prep): one stacked GEMM per node: {x,u,v} = Ws @ h + bs.
// 8 nodes per warp-iteration; lane owns 6 outputs j = lane + 32g, g=0..5
// (g 0,1 -> x ; 2,3 -> u ; 4,5 -> v).  Weights padded to 68 floats/row.
// Writes: d_out = x (fp32 residual), g_xc = bf16(x), g_uv = bf16(u)||bf16(v).
// ---------------------------------------------------------------------------
#define PREP_SMEM ((192 * 68 + 192) * 4 + 8 * 8 * 64 * 4)   // 69,376 B

__global__ void __launch_bounds__(256, 2)
prep_kernel(const float* __restrict__ h,
            float* __restrict__ out_res)
{
    extern __shared__ float smem[];
    float*  sWs = smem;                    // 192*68
    float*  sbs = sWs + 192 * 68;          // 192
    float4* sH  = (float4*)(sbs + 192);    // [8 warps][8 nodes][16 f4]

    const int tid = threadIdx.x;
    for (int i = tid; i < 192 * 64; i += 256)
        sWs[(i >> 6) * 68 + (i & 63)] = g_Ws[i];
    if (tid < 192) sbs[tid] = g_bs[tid];
    __syncthreads();

    const int lane = tid & 31;
    const int w    = tid >> 5;
    const int warpGlobal = blockIdx.x * 8 + w;
    const int nWarps     = gridDim.x * 8;

    const float4* wp[6];
    float bj[6];
    #pragma unroll
    for (int g = 0; g < 6; g++) {
        wp[g] = ((const float4*)sWs) + (g * 32 + lane) * 17;
        bj[g] = sbs[g * 32 + lane];
    }
    const float4* hf4 = (const float4*)h;
    float4* sHw = sH + w * (8 * 16);

    for (int nb = warpGlobal * 8; nb < N_NODES; nb += nWarps * 8) {
        // Stage 8 h rows (2 nodes per half-warp, 4 passes)
        #pragma unroll
        for (int ep = 0; ep < 8; ep += 2) {
            const int e  = ep + (lane >> 4);
            const int li = lane & 15;
            sHw[e * 16 + li] = hf4[(size_t)(nb + e) * 16 + li];
        }
        __syncwarp();

        float acc[6][8];
        #pragma unroll
        for (int g = 0; g < 6; g++)
            #pragma unroll
            for (int e = 0; e < 8; e++) acc[g][e] = bj[g];

        #pragma unroll 2
        for (int kk = 0; kk < 16; kk++) {
            float4 wr[6];
            #pragma unroll
            for (int g = 0; g < 6; g++) wr[g] = wp[g][kk];
            #pragma unroll
            for (int e = 0; e < 8; e++) {
                const float4 xv = sHw[e * 16 + kk];   // warp-uniform broadcast
                #pragma unroll
                for (int g = 0; g < 6; g++) {
                    acc[g][e] = fmaf(wr[g].x, xv.x, acc[g][e]);
                    acc[g][e] = fmaf(wr[g].y, xv.y, acc[g][e]);
                    acc[g][e] = fmaf(wr[g].z, xv.z, acc[g][e]);
                    acc[g][e] = fmaf(wr[g].w, xv.w, acc[g][e]);
                }
            }
        }

        #pragma unroll
        for (int e = 0; e < 8; e++) {
            const size_t n64  = (size_t)(nb + e) * 64;
            const size_t n128 = (size_t)(nb + e) * 128;
            // residual (fp32, exact)
            out_res[n64 + lane]      = acc[0][e];
            out_res[n64 + lane + 32] = acc[1][e];
            // bf16 copies for edge kernel
            g_xc[n64 + lane]       = __float2bfloat16(acc[0][e]);
            g_xc[n64 + lane + 32]  = __float2bfloat16(acc[1][e]);
            g_uv[n128 + lane]      = __float2bfloat16(acc[2][e]);
            g_uv[n128 + lane + 32] = __float2bfloat16(acc[3][e]);
            g_uv[n128 + 64 + lane]      = __float2bfloat16(acc[4][e]);
            g_uv[n128 + 64 + lane + 32] = __float2bfloat16(acc[5][e]);
        }
        __syncwarp();
    }
}

// ---------------------------------------------------------------------------
// Kernel 2 (edge): t = u[row]+v[col]+wd*d+b1; att = sig(W2.silu(t)+b2);
// red.global.add.v4 of att*x_col into d_out[row].
// Half-warp per edge (lane li owns dims 4li..4li+3), 4 edges per warp-iter.
// u,v,x gathers are bf16 (8B per lane).
// ---------------------------------------------------------------------------
__global__ void edge_kernel(const float* __restrict__ dist,
                            const int* __restrict__ edges,  // int32 [2][E]
                            const float* __restrict__ emask,
                            const float* __restrict__ W1,   // [64][129]
                            const float* __restrict__ b1,
                            const float* __restrict__ W2,   // [64]
                            const float* __restrict__ b2p,
                            float* __restrict__ agg)        // d_out
{
    const int lane = threadIdx.x & 31;
    const int w    = threadIdx.x >> 5;
    const int hw   = lane >> 4;      // which edge of the pair
    const int li   = lane & 15;      // dim group within edge

    const float4 w2_4 = ((const float4*)W2)[li];
    const float4 b1_4 = ((const float4*)b1)[li];
    float4 wd_4;
    wd_4.x = __ldg(W1 + (size_t)(li * 4 + 0) * 129 + 128);
    wd_4.y = __ldg(W1 + (size_t)(li * 4 + 1) * 129 + 128);
    wd_4.z = __ldg(W1 + (size_t)(li * 4 + 2) * 129 + 128);
    wd_4.w = __ldg(W1 + (size_t)(li * 4 + 3) * 129 + 128);
    const float b2 = b2p[0];

    const uint2* uvp = (const uint2*)g_uv;   // 32 uint2 per node (u:0-15, v:16-31)
    const uint2* xcp = (const uint2*)g_xc;   // 16 uint2 per node

    const int warpGlobal = blockIdx.x * 8 + w;
    const int nWarps     = gridDim.x * 8;

    for (int eb = warpGlobal * 4; eb < E_EDGES; eb += nWarps * 4) {
        #pragma unroll
        for (int s = 0; s < 2; s++) {
            const int e   = eb + s * 2 + hw;            // E%4==0 -> in range
            const int row = __ldg(edges + e);
            const int col = __ldg(edges + E_EDGES + e);
            const float d  = __ldg(dist + e);
            const float em = __ldg(emask + e);

            const float4 u4 = bf16x4_to_f4(__ldg(uvp + (size_t)row * 32 + li));
            const float4 v4 = bf16x4_to_f4(__ldg(uvp + (size_t)col * 32 + 16 + li));
            const float4 x4 = bf16x4_to_f4(__ldg(xcp + (size_t)col * 16 + li));

            float4 t;
            t.x = fmaf(d, wd_4.x, u4.x + v4.x + b1_4.x);
            t.y = fmaf(d, wd_4.y, u4.y + v4.y + b1_4.y);
            t.z = fmaf(d, wd_4.z, u4.z + v4.z + b1_4.z);
            t.w = fmaf(d, wd_4.w, u4.w + v4.w + b1_4.w);

            const float h0 = t.x * fsig(t.x);
            const float h1 = t.y * fsig(t.y);
            const float h2 = t.z * fsig(t.z);
            const float h3 = t.w * fsig(t.w);

            float p = fmaf(h0, w2_4.x,
                      fmaf(h1, w2_4.y,
                      fmaf(h2, w2_4.z, h3 * w2_4.w)));
            #pragma unroll
            for (int off = 8; off; off >>= 1)          // reduce within 16 lanes
                p += __shfl_xor_sync(0xffffffffu, p, off);

            const float att = fsig(p + b2) * em * NORM_INV;

            float* dst = agg + (size_t)row * 64 + li * 4;
            red_add_v4(dst, x4.x * att, x4.y * att, x4.z * att, x4.w * att);
        }
    }
}

// ---------------------------------------------------------------------------
// Kernel 3: in-place LayerNorm + SiLU on d_out.
// ---------------------------------------------------------------------------
__global__ void ln_kernel(const float* __restrict__ g,
                          const float* __restrict__ bln,
                          float* __restrict__ io)
{
    const int lane = threadIdx.x & 31;
    const int w    = threadIdx.x >> 5;
    const int row  = blockIdx.x * 8 + w;
    if (row >= N_NODES) return;

    float2 v = ((const float2*)io)[(size_t)row * 32 + lane];

    float s = v.x + v.y;
    #pragma unroll
    for (int off = 16; off; off >>= 1)
        s += __shfl_xor_sync(0xffffffffu, s, off);
    const float mu = s * (1.0f / 64.0f);

    const float dx = v.x - mu, dy = v.y - mu;
    float q = dx * dx + dy * dy;
    #pragma unroll
    for (int off = 16; off; off >>= 1)
        q += __shfl_xor_sync(0xffffffffu, q, off);
    const float rs = rsqrtf(q * (1.0f / 64.0f) + LN_EPS);

    const float y0 = fmaf(dx * rs, __ldg(g + 2 * lane),     __ldg(bln + 2 * lane));
    const float y1 = fmaf(dy * rs, __ldg(g + 2 * lane + 1), __ldg(bln + 2 * lane + 1));

    float2 o;
    o.x = y0 * fsig(y0);
    o.y = y1 * fsig(y1);
    ((float2*)io)[(size_t)row * 32 + lane] = o;
}

// ---------------------------------------------------------------------------
// Launch: compose -> prep -> edge -> layernorm.
// ---------------------------------------------------------------------------
extern "C" void kernel_launch(void* const* d_in, const int* in_sizes, int n_in,
                              void* d_out, int out_size)
{
    const float* h     = (const float*)d_in[0];
    const float* dist  = (const float*)d_in[1];
    const int*   edges = (const int*)d_in[2];   // JAX x64-disabled => int32
    /* d_in[3] node_mask: unused by the reference */
    const float* emask = (const float*)d_in[4];
    const float* Wlin  = (const float*)d_in[5];
    const float* blin  = (const float*)d_in[6];
    const float* W1    = (const float*)d_in[7];
    const float* b1    = (const float*)d_in[8];
    const float* W2    = (const float*)d_in[9];
    const float* b2    = (const float*)d_in[10];
    const float* lng   = (const float*)d_in[11];
    const float* lnb   = (const float*)d_in[12];
    float* out = (float*)d_out;

    cudaFuncSetAttribute(prep_kernel,
                         cudaFuncAttributeMaxDynamicSharedMemorySize, PREP_SMEM);

    compose_kernel<<<16, 256>>>(Wlin, blin, W1);
    prep_kernel<<<592, 256, PREP_SMEM>>>(h, out);
    edge_kernel<<<1184, 256>>>(dist, edges, emask, W1, b1, W2, b2, out);
    ln_kernel<<<(N_NODES + 7) / 8, 256>>>(lng, lnb, out);
}